// round 13
// baseline (speedup 1.0000x reference)
#include <cuda_runtime.h>
#include <cuda_bf16.h>
#include <math.h>

// ---------------- problem constants ----------------
#define CUTOFF        7.0
#define LJ_SIGMA      3.1589
#define LJ_EPSILON    0.1852
#define M_GAMMA       0.73612
#define M_CHARGE      1.1128
#define OH_BOND_EQ    0.9419f
#define OH_BOND_K     1059.162f
#define OH_BOND_ALPHA 2.287f
#define HOH_ANGLE_EQ  1.87448f
#define HOH_ANGLE_K   87.85f
#define P3M_SMEARING  1.4
#define PREFACTOR     332.0637133

#define NMOL_MAX 13824   // 24^3

static constexpr double D_SIG2  = LJ_SIGMA * LJ_SIGMA;
static constexpr double D_SIG6  = D_SIG2 * D_SIG2 * D_SIG2;
static constexpr double D_T     = LJ_SIGMA / CUTOFF;
static constexpr double D_T2    = D_T * D_T;
static constexpr double D_SC6   = D_T2 * D_T2 * D_T2;
static constexpr double D_SHIFT = -4.0 * LJ_EPSILON * D_SC6 * (D_SC6 - 1.0);
static constexpr double D_INVSS = 0.7071067811865475 / P3M_SMEARING;
static constexpr double D_OMF   = (1.0 - M_GAMMA) * 0.5;

#define F_SIG6   ((float)D_SIG6)
#define F_SHIFT  ((float)D_SHIFT)
#define F_INVSS  ((float)D_INVSS)
#define F_OMF    ((float)D_OMF)
#define F_QO     ((float)(-M_CHARGE))
#define F_QH     ((float)(0.5 * M_CHARGE))
#define F_PREF   ((float)PREFACTOR)
#define F_4EPS   ((float)(4.0 * LJ_EPSILON))

#define TB      256
#define BPSM    4
#define NB      (148 * BPSM)   // co-resident under launch_bounds(256,4)
#define U       2              // pairs per pipeline batch

// ---------------- device state ----------------
__device__ double   g_energy   = 0.0;
__device__ float4   g_om[NMOL_MAX];
__device__ unsigned g_arrive1  = 0;
__device__ unsigned g_release1 = 0;   // monotonic across graph replays
__device__ unsigned g_arrive2  = 0;

// ---------------- grid barrier (replay-safe, all blocks resident) ----------------
__device__ __forceinline__ void grid_barrier() {
    __syncthreads();
    if (threadIdx.x == 0) {
        volatile unsigned* rel = &g_release1;
        unsigned old = *rel;
        __threadfence();
        unsigned t = atomicAdd(&g_arrive1, 1u);
        if (t == NB - 1) {
            g_arrive1 = 0;
            __threadfence();
            atomicAdd(&g_release1, 1u);
        } else {
            while (*rel == old) { }
        }
        __threadfence();
    }
    __syncthreads();
}

__device__ __forceinline__ float bond_e(float r) {
    float dr  = r - OH_BOND_EQ;
    float adr = dr * OH_BOND_ALPHA;
    return 0.5f * OH_BOND_K * dr * dr * (1.0f - adr + adr * adr * (7.0f / 12.0f));
}

// Numerical-Recipes erfcc, relative error ~1e-6 in f32, x >= 0.
__device__ __forceinline__ float fast_erfc(float x) {
    float t = __fdividef(1.0f, fmaf(0.5f, x, 1.0f));
    float p = fmaf(t, 0.17087277f, -0.82215223f);
    p = fmaf(t, p,  1.48851587f);
    p = fmaf(t, p, -1.13520398f);
    p = fmaf(t, p,  0.27886807f);
    p = fmaf(t, p, -0.18628806f);
    p = fmaf(t, p,  0.09678418f);
    p = fmaf(t, p,  0.37409196f);
    p = fmaf(t, p,  1.00002368f);
    p = fmaf(t, p, -1.26551223f);
    return t * __expf(fmaf(-x, x, p));
}

// raw stream batch
struct Raw {
    int   i[U], j[U];
    float dx[U], dy[U], dz[U];
};
// gathered om vectors + flags (gathers issued, consumed next iteration)
struct Gat {
    float gix[U], giy[U], giz[U];
    float gjx[U], gjy[U], gjz[U];
    bool  iO[U], jO[U];
};

__device__ __forceinline__ void load_batch(Raw& r,
                                           const int* __restrict__ ni,
                                           const int* __restrict__ nj,
                                           const float* __restrict__ dij,
                                           int base, int stride) {
    #pragma unroll
    for (int k = 0; k < U; k++) {
        int p = base + k * stride;
        r.i[k] = __ldcs(ni + p);
        r.j[k] = __ldcs(nj + p);
    }
    #pragma unroll
    for (int k = 0; k < U; k++) {
        const float* q = dij + 3 * (base + k * stride);
        r.dx[k] = __ldcs(q);
        r.dy[k] = __ldcs(q + 1);
        r.dz[k] = __ldcs(q + 2);
    }
}

__device__ __forceinline__ void gather_batch(Gat& g, const Raw& r) {
    const float4 f4z = make_float4(0.0f, 0.0f, 0.0f, 0.0f);
    #pragma unroll
    for (int k = 0; k < U; k++) {
        int mi = r.i[k] / 3;
        int mj = r.j[k] / 3;
        g.iO[k] = (r.i[k] == 3 * mi);
        g.jO[k] = (r.j[k] == 3 * mj);
        float4 gi = g.iO[k] ? g_om[mi] : f4z;
        float4 gj = g.jO[k] ? g_om[mj] : f4z;
        g.gix[k] = gi.x; g.giy[k] = gi.y; g.giz[k] = gi.z;
        g.gjx[k] = gj.x; g.gjy[k] = gj.y; g.gjz[k] = gj.z;
    }
}

__device__ __forceinline__ float compute_batch(const Raw& r, const Gat& g) {
    float facc = 0.0f;
    #pragma unroll
    for (int k = 0; k < U; k++) {
        float ox = r.dx[k] + g.gjx[k] - g.gix[k];
        float oy = r.dy[k] + g.gjy[k] - g.giy[k];
        float oz = r.dz[k] + g.gjz[k] - g.giz[k];

        float qq = (g.iO[k] ? F_QO : F_QH) * (g.jO[k] ? F_QO : F_QH);

        float md2  = ox * ox + oy * oy + oz * oz;
        float rinv = rsqrtf(md2);
        float md   = md2 * rinv;
        facc += F_PREF * qq * fast_erfc(md * F_INVSS) * rinv;

        if (g.iO[k] && g.jO[k]) {
            float r2 = r.dx[k] * r.dx[k] + r.dy[k] * r.dy[k] + r.dz[k] * r.dz[k];
            float r6 = r2 * r2 * r2;
            float i6 = __fdividef(F_SIG6, r6);
            facc += F_4EPS * (i6 * i6 - i6) + F_SHIFT;
        }
    }
    return facc;
}

// scalar pair energy (tail path)
__device__ __forceinline__ float pair_scalar(const int* ni, const int* nj,
                                             const float* dij, int p) {
    int i = ni[p], j = nj[p];
    int mi = i / 3, mj = j / 3;
    bool iO = (i == 3 * mi), jO = (j == 3 * mj);
    const float* q = dij + 3 * p;
    float dx = q[0], dy = q[1], dz = q[2];
    float ox = dx, oy = dy, oz = dz;
    if (jO) { float4 g = g_om[mj]; ox += g.x; oy += g.y; oz += g.z; }
    if (iO) { float4 g = g_om[mi]; ox -= g.x; oy -= g.y; oz -= g.z; }
    float qq   = (iO ? F_QO : F_QH) * (jO ? F_QO : F_QH);
    float md2  = ox * ox + oy * oy + oz * oz;
    float rinv = rsqrtf(md2);
    float md   = md2 * rinv;
    float e    = F_PREF * qq * fast_erfc(md * F_INVSS) * rinv;
    if (iO && jO) {
        float r2 = dx * dx + dy * dy + dz * dz;
        float r6 = r2 * r2 * r2;
        float i6 = __fdividef(F_SIG6, r6);
        e += F_4EPS * (i6 * i6 - i6) + F_SHIFT;
    }
    return e;
}

// ---------------- fused kernel ----------------
__global__ __launch_bounds__(TB, BPSM)
void k_fused(const float* __restrict__ dij,
             const int* __restrict__ ni,
             const int* __restrict__ nj,
             int n, int n_mol,
             float* __restrict__ out) {
    const int tid  = threadIdx.x;
    const int gtid = blockIdx.x * TB + tid;
    double acc = 0.0;

    // ---- Phase 1: per-molecule terms + M-site offsets ----
    // Pair-list order: pair m = (O_m,H1_m) = doh1[m]; pair n_mol+m = (O_m,H2_m) = doh2[m]
    if (gtid < n_mol) {
        int m = gtid;
        const float* p1 = dij + 3 * m;
        const float* p2 = dij + 3 * (n_mol + m);
        float ax = p1[0], ay = p1[1], az = p1[2];
        float bx = p2[0], by = p2[1], bz = p2[2];

        float r1 = sqrtf(ax * ax + ay * ay + az * az);
        float r2 = sqrtf(bx * bx + by * by + bz * bz);
        float eb = bond_e(r1) + bond_e(r2);

        float dotab = ax * bx + ay * by + az * bz;
        float ang = acosf(dotab / (r1 * r2));
        float da = ang - HOH_ANGLE_EQ;
        eb += 0.5f * HOH_ANGLE_K * da * da;

        float ox = F_OMF * (ax + bx);
        float oy = F_OMF * (ay + by);
        float oz = F_OMF * (az + bz);
        g_om[m] = make_float4(ox, oy, oz, 0.0f);

        float m1x = ax - ox, m1y = ay - oy, m1z = az - oz;
        float m2x = bx - ox, m2y = by - oy, m2z = bz - oz;
        float hhx = ax - bx, hhy = ay - by, hhz = az - bz;
        float inv_mh = rsqrtf(m1x * m1x + m1y * m1y + m1z * m1z)
                     + rsqrtf(m2x * m2x + m2y * m2y + m2z * m2z);
        float inv_hh = rsqrtf(hhx * hhx + hhy * hhy + hhz * hhz);
        float eself = (inv_mh * F_QO + inv_hh * F_QH) * F_QH * F_PREF;
        acc = (double)(eb - eself);
    }

    grid_barrier();   // g_om globally visible

    // ---- Phase 2: 3-stage software pipeline over the pair stream ----
    const int stride  = NB * TB;
    const int bstride = stride * U;
    #define FULLB(b) ((b) + (U - 1) * stride < n)

    int bA = gtid;               // t   : compute
    int bB = bA + bstride;       // t+1 : gathered
    int bC = bB + bstride;       // t+2 : loading

    Raw rA, rB, rC;
    Gat gA, gB;
    bool vA = FULLB(bA), vB = FULLB(bB), vC = FULLB(bC);

    if (vA) load_batch(rA, ni, nj, dij, bA, stride);
    if (vB) load_batch(rB, ni, nj, dij, bB, stride);
    if (vA) gather_batch(gA, rA);

    while (vA) {
        if (vC) load_batch(rC, ni, nj, dij, bC, stride);   // loads for t+2
        if (vB) gather_batch(gB, rB);                      // gathers for t+1
        acc += (double)compute_batch(rA, gA);              // compute t

        rA = rB; gA = gB; rB = rC;
        bA = bB; bB = bC; bC += bstride;
        vA = vB; vB = vC; vC = FULLB(bC);
    }

    // tail: remaining pairs (non-full batches), scalar
    for (int p = bA; p < n; p += stride)
        acc += (double)pair_scalar(ni, nj, dij, p);

    // ---- Reduce: block -> global, last block writes result ----
    #pragma unroll
    for (int o = 16; o > 0; o >>= 1)
        acc += __shfl_down_sync(0xffffffffu, acc, o);
    __shared__ double s_red[TB / 32];
    int lane = tid & 31;
    int w    = tid >> 5;
    if (lane == 0) s_red[w] = acc;
    __syncthreads();
    if (w == 0) {
        acc = (lane < TB / 32) ? s_red[lane] : 0.0;
        #pragma unroll
        for (int o = 16; o > 0; o >>= 1)
            acc += __shfl_down_sync(0xffffffffu, acc, o);
        if (lane == 0) {
            atomicAdd(&g_energy, acc);
            __threadfence();
            unsigned t = atomicAdd(&g_arrive2, 1u);
            if (t == NB - 1) {
                g_arrive2 = 0;
                unsigned long long v =
                    atomicExch((unsigned long long*)&g_energy, 0ULL);
                out[0] = (float)__longlong_as_double(v);
            }
        }
    }
}

// ---------------- launch ----------------
extern "C" void kernel_launch(void* const* d_in, const int* in_sizes, int n_in,
                              void* d_out, int out_size) {
    const float* dij = (const float*)d_in[0];
    const int*   ni  = (const int*)d_in[2];
    const int*   nj  = (const int*)d_in[3];
    int n_pairs = in_sizes[2];
    int n_mol   = in_sizes[1] / 3;
    float* out  = (float*)d_out;

    k_fused<<<NB, TB>>>(dij, ni, nj, n_pairs, n_mol, out);
}

// round 14
// speedup vs baseline: 1.0671x; 1.0671x over previous
#include <cuda_runtime.h>
#include <cuda_bf16.h>
#include <math.h>

// ---------------- problem constants ----------------
#define CUTOFF        7.0
#define LJ_SIGMA      3.1589
#define LJ_EPSILON    0.1852
#define M_GAMMA       0.73612
#define M_CHARGE      1.1128
#define OH_BOND_EQ    0.9419f
#define OH_BOND_K     1059.162f
#define OH_BOND_ALPHA 2.287f
#define HOH_ANGLE_EQ  1.87448f
#define HOH_ANGLE_K   87.85f
#define P3M_SMEARING  1.4
#define PREFACTOR     332.0637133

#define NMOL_MAX 13824   // 24^3

static constexpr double D_SIG2  = LJ_SIGMA * LJ_SIGMA;
static constexpr double D_SIG6  = D_SIG2 * D_SIG2 * D_SIG2;
static constexpr double D_T     = LJ_SIGMA / CUTOFF;
static constexpr double D_T2    = D_T * D_T;
static constexpr double D_SC6   = D_T2 * D_T2 * D_T2;
static constexpr double D_SHIFT = -4.0 * LJ_EPSILON * D_SC6 * (D_SC6 - 1.0);
static constexpr double D_INVSS = 0.7071067811865475 / P3M_SMEARING;
static constexpr double D_OMF   = (1.0 - M_GAMMA) * 0.5;

#define F_SIG6   ((float)D_SIG6)
#define F_SHIFT  ((float)D_SHIFT)
#define F_INVSS  ((float)D_INVSS)
#define F_OMF    ((float)D_OMF)
#define F_QO     ((float)(-M_CHARGE))
#define F_QH     ((float)(0.5 * M_CHARGE))
#define F_PREF   ((float)PREFACTOR)
#define F_4EPS   ((float)(4.0 * LJ_EPSILON))

#define TB   1024
#define NB   148            // 1 block per SM -> trivially co-resident
#define U    2              // pairs per pipeline batch
#define SMEM_BYTES (3 * NMOL_MAX * 4)   // 165,888 B packed float3 om table

// ---------------- device state ----------------
__device__ double   g_energy   = 0.0;
__device__ float    g_om3[3 * NMOL_MAX];
__device__ unsigned g_arrive1  = 0;
__device__ unsigned g_release1 = 0;   // monotonic across graph replays
__device__ unsigned g_arrive2  = 0;

// ---------------- grid barrier (replay-safe, all blocks resident) ----------------
__device__ __forceinline__ void grid_barrier() {
    __syncthreads();
    if (threadIdx.x == 0) {
        volatile unsigned* rel = &g_release1;
        unsigned old = *rel;
        __threadfence();
        unsigned t = atomicAdd(&g_arrive1, 1u);
        if (t == NB - 1) {
            g_arrive1 = 0;
            __threadfence();
            atomicAdd(&g_release1, 1u);
        } else {
            while (*rel == old) { }
        }
        __threadfence();
    }
    __syncthreads();
}

__device__ __forceinline__ float bond_e(float r) {
    float dr  = r - OH_BOND_EQ;
    float adr = dr * OH_BOND_ALPHA;
    return 0.5f * OH_BOND_K * dr * dr * (1.0f - adr + adr * adr * (7.0f / 12.0f));
}

// Numerical-Recipes erfcc, relative error ~1e-6 in f32, x >= 0.
__device__ __forceinline__ float fast_erfc(float x) {
    float t = __fdividef(1.0f, fmaf(0.5f, x, 1.0f));
    float p = fmaf(t, 0.17087277f, -0.82215223f);
    p = fmaf(t, p,  1.48851587f);
    p = fmaf(t, p, -1.13520398f);
    p = fmaf(t, p,  0.27886807f);
    p = fmaf(t, p, -0.18628806f);
    p = fmaf(t, p,  0.09678418f);
    p = fmaf(t, p,  0.37409196f);
    p = fmaf(t, p,  1.00002368f);
    p = fmaf(t, p, -1.26551223f);
    return t * __expf(fmaf(-x, x, p));
}

struct Raw {
    int   i[U], j[U];
    float dx[U], dy[U], dz[U];
};

__device__ __forceinline__ void load_batch(Raw& r,
                                           const int* __restrict__ ni,
                                           const int* __restrict__ nj,
                                           const float* __restrict__ dij,
                                           int base, int stride) {
    #pragma unroll
    for (int k = 0; k < U; k++) {
        int p = base + k * stride;
        r.i[k] = __ldcs(ni + p);
        r.j[k] = __ldcs(nj + p);
    }
    #pragma unroll
    for (int k = 0; k < U; k++) {
        const float* q = dij + 3 * (base + k * stride);
        r.dx[k] = __ldcs(q);
        r.dy[k] = __ldcs(q + 1);
        r.dz[k] = __ldcs(q + 2);
    }
}

// ---------------- fused kernel ----------------
__global__ __launch_bounds__(TB, 1)
void k_fused(const float* __restrict__ dij,
             const int* __restrict__ ni,
             const int* __restrict__ nj,
             int n, int n_mol,
             float* __restrict__ out) {
    extern __shared__ float s_om[];           // packed float3 om table
    __shared__ double s_red[TB / 32];

    const int tid  = threadIdx.x;
    const int gtid = blockIdx.x * TB + tid;
    double acc = 0.0;

    // ---- Phase 1: per-molecule terms + M-site offsets (to global) ----
    // Pair-list order: pair m = (O_m,H1_m) = doh1[m]; pair n_mol+m = (O_m,H2_m) = doh2[m]
    if (gtid < n_mol) {
        int m = gtid;
        const float* p1 = dij + 3 * m;
        const float* p2 = dij + 3 * (n_mol + m);
        float ax = p1[0], ay = p1[1], az = p1[2];
        float bx = p2[0], by = p2[1], bz = p2[2];

        float r1 = sqrtf(ax * ax + ay * ay + az * az);
        float r2 = sqrtf(bx * bx + by * by + bz * bz);
        float eb = bond_e(r1) + bond_e(r2);

        float dotab = ax * bx + ay * by + az * bz;
        float ang = acosf(dotab / (r1 * r2));
        float da = ang - HOH_ANGLE_EQ;
        eb += 0.5f * HOH_ANGLE_K * da * da;

        float ox = F_OMF * (ax + bx);
        float oy = F_OMF * (ay + by);
        float oz = F_OMF * (az + bz);
        g_om3[3 * m + 0] = ox;
        g_om3[3 * m + 1] = oy;
        g_om3[3 * m + 2] = oz;

        float m1x = ax - ox, m1y = ay - oy, m1z = az - oz;
        float m2x = bx - ox, m2y = by - oy, m2z = bz - oz;
        float hhx = ax - bx, hhy = ay - by, hhz = az - bz;
        float inv_mh = rsqrtf(m1x * m1x + m1y * m1y + m1z * m1z)
                     + rsqrtf(m2x * m2x + m2y * m2y + m2z * m2z);
        float inv_hh = rsqrtf(hhx * hhx + hhy * hhy + hhz * hhz);
        float eself = (inv_mh * F_QO + inv_hh * F_QH) * F_QH * F_PREF;
        acc = (double)(eb - eself);
    }

    grid_barrier();   // g_om3 globally visible

    // ---- Copy om table into shared (coalesced float4, L2-broadcast) ----
    {
        const int n16 = (3 * n_mol) / 4;       // 41472/4 = 10368 float4s
        const float4* src = (const float4*)g_om3;
        float4*       dst = (float4*)s_om;
        for (int k = tid; k < n16; k += TB)
            dst[k] = __ldg(src + k);
        // tail floats (3*n_mol not multiple of 4)
        for (int k = (n16 * 4) + tid; k < 3 * n_mol; k += TB)
            s_om[k] = g_om3[k];
    }
    __syncthreads();

    // ---- Phase 2: 2-stage pipelined pair stream, smem gathers ----
    const int stride = NB * TB;
    int base = gtid;
    bool valid = (base + (U - 1) * stride < n);

    Raw cur;
    if (valid) load_batch(cur, ni, nj, dij, base, stride);

    while (valid) {
        int  nbase  = base + U * stride;
        bool nvalid = (nbase + (U - 1) * stride < n);

        // stage 1: smem gathers for CURRENT (idx regs resident)
        bool  iO[U], jO[U];
        float ox[U], oy[U], oz[U];
        #pragma unroll
        for (int k = 0; k < U; k++) {
            int mi = cur.i[k] / 3;
            int mj = cur.j[k] / 3;
            iO[k] = (cur.i[k] == 3 * mi);
            jO[k] = (cur.j[k] == 3 * mj);
            ox[k] = cur.dx[k]; oy[k] = cur.dy[k]; oz[k] = cur.dz[k];
            if (jO[k]) {
                int b = 3 * mj;
                ox[k] += s_om[b]; oy[k] += s_om[b + 1]; oz[k] += s_om[b + 2];
            }
            if (iO[k]) {
                int b = 3 * mi;
                ox[k] -= s_om[b]; oy[k] -= s_om[b + 1]; oz[k] -= s_om[b + 2];
            }
        }

        // stage 2: prefetch NEXT batch (hides stream latency under compute)
        Raw nxt;
        if (nvalid) load_batch(nxt, ni, nj, dij, nbase, stride);

        // stage 3: compute CURRENT
        float facc = 0.0f;
        #pragma unroll
        for (int k = 0; k < U; k++) {
            float qq   = (iO[k] ? F_QO : F_QH) * (jO[k] ? F_QO : F_QH);
            float md2  = ox[k] * ox[k] + oy[k] * oy[k] + oz[k] * oz[k];
            float rinv = rsqrtf(md2);
            float md   = md2 * rinv;
            facc += F_PREF * qq * fast_erfc(md * F_INVSS) * rinv;

            if (iO[k] && jO[k]) {
                float r2 = cur.dx[k] * cur.dx[k] + cur.dy[k] * cur.dy[k]
                         + cur.dz[k] * cur.dz[k];
                float r6 = r2 * r2 * r2;
                float i6 = __fdividef(F_SIG6, r6);
                facc += F_4EPS * (i6 * i6 - i6) + F_SHIFT;
            }
        }
        acc += (double)facc;

        cur   = nxt;
        base  = nbase;
        valid = nvalid;
    }

    // tail (scalar, smem gathers)
    for (int p = base; p < n; p += stride) {
        int i = ni[p], j = nj[p];
        int mi = i / 3, mj = j / 3;
        bool iO = (i == 3 * mi), jO = (j == 3 * mj);
        const float* q = dij + 3 * p;
        float dx = q[0], dy = q[1], dz = q[2];
        float ox = dx, oy = dy, oz = dz;
        if (jO) { int b = 3 * mj; ox += s_om[b]; oy += s_om[b + 1]; oz += s_om[b + 2]; }
        if (iO) { int b = 3 * mi; ox -= s_om[b]; oy -= s_om[b + 1]; oz -= s_om[b + 2]; }
        float qq   = (iO ? F_QO : F_QH) * (jO ? F_QO : F_QH);
        float md2  = ox * ox + oy * oy + oz * oz;
        float rinv = rsqrtf(md2);
        float md   = md2 * rinv;
        float e    = F_PREF * qq * fast_erfc(md * F_INVSS) * rinv;
        if (iO && jO) {
            float r2 = dx * dx + dy * dy + dz * dz;
            float r6 = r2 * r2 * r2;
            float i6 = __fdividef(F_SIG6, r6);
            e += F_4EPS * (i6 * i6 - i6) + F_SHIFT;
        }
        acc += (double)e;
    }

    // ---- Reduce: block -> global, last block writes result ----
    #pragma unroll
    for (int o = 16; o > 0; o >>= 1)
        acc += __shfl_down_sync(0xffffffffu, acc, o);
    int lane = tid & 31;
    int w    = tid >> 5;
    if (lane == 0) s_red[w] = acc;
    __syncthreads();
    if (w == 0) {
        acc = (lane < TB / 32) ? s_red[lane] : 0.0;
        #pragma unroll
        for (int o = 16; o > 0; o >>= 1)
            acc += __shfl_down_sync(0xffffffffu, acc, o);
        if (lane == 0) {
            atomicAdd(&g_energy, acc);
            __threadfence();
            unsigned t = atomicAdd(&g_arrive2, 1u);
            if (t == NB - 1) {
                g_arrive2 = 0;
                unsigned long long v =
                    atomicExch((unsigned long long*)&g_energy, 0ULL);
                out[0] = (float)__longlong_as_double(v);
            }
        }
    }
}

// ---------------- launch ----------------
extern "C" void kernel_launch(void* const* d_in, const int* in_sizes, int n_in,
                              void* d_out, int out_size) {
    const float* dij = (const float*)d_in[0];
    const int*   ni  = (const int*)d_in[2];
    const int*   nj  = (const int*)d_in[3];
    int n_pairs = in_sizes[2];
    int n_mol   = in_sizes[1] / 3;
    float* out  = (float*)d_out;

    static int smem_set = 0;
    if (!smem_set) {
        cudaFuncSetAttribute(k_fused, cudaFuncAttributeMaxDynamicSharedMemorySize,
                             SMEM_BYTES);
        smem_set = 1;
    }
    k_fused<<<NB, TB, SMEM_BYTES>>>(dij, ni, nj, n_pairs, n_mol, out);
}

// round 15
// speedup vs baseline: 1.1824x; 1.1081x over previous
#include <cuda_runtime.h>
#include <cuda_bf16.h>
#include <math.h>

// ---------------- problem constants ----------------
#define CUTOFF        7.0
#define LJ_SIGMA      3.1589
#define LJ_EPSILON    0.1852
#define M_GAMMA       0.73612
#define M_CHARGE      1.1128
#define OH_BOND_EQ    0.9419f
#define OH_BOND_K     1059.162f
#define OH_BOND_ALPHA 2.287f
#define HOH_ANGLE_EQ  1.87448f
#define HOH_ANGLE_K   87.85f
#define P3M_SMEARING  1.4
#define PREFACTOR     332.0637133

#define NMOL_MAX 13824   // 24^3

static constexpr double D_SIG2  = LJ_SIGMA * LJ_SIGMA;
static constexpr double D_SIG6  = D_SIG2 * D_SIG2 * D_SIG2;
static constexpr double D_T     = LJ_SIGMA / CUTOFF;
static constexpr double D_T2    = D_T * D_T;
static constexpr double D_SC6   = D_T2 * D_T2 * D_T2;
static constexpr double D_SHIFT = -4.0 * LJ_EPSILON * D_SC6 * (D_SC6 - 1.0);
static constexpr double D_INVSS = 0.7071067811865475 / P3M_SMEARING;
static constexpr double D_OMF   = (1.0 - M_GAMMA) * 0.5;

#define F_SIG6   ((float)D_SIG6)
#define F_SHIFT  ((float)D_SHIFT)
#define F_INVSS  ((float)D_INVSS)
#define F_OMF    ((float)D_OMF)
#define F_QO     ((float)(-M_CHARGE))
#define F_QH     ((float)(0.5 * M_CHARGE))
#define F_PREF   ((float)PREFACTOR)
#define F_4EPS   ((float)(4.0 * LJ_EPSILON))

#define TB      256
#define BPSM    4
#define NB      (148 * BPSM)   // co-resident under launch_bounds(256,4)

// ---------------- device state ----------------
__device__ double   g_energy   = 0.0;
__device__ float4   g_om[NMOL_MAX];
__device__ unsigned g_arrive1  = 0;
__device__ unsigned g_release1 = 0;   // monotonic across graph replays
__device__ unsigned g_arrive2  = 0;

// ---------------- grid barrier (replay-safe, all blocks resident) ----------------
__device__ __forceinline__ void grid_barrier() {
    __syncthreads();
    if (threadIdx.x == 0) {
        volatile unsigned* rel = &g_release1;
        unsigned old = *rel;
        __threadfence();
        unsigned t = atomicAdd(&g_arrive1, 1u);
        if (t == NB - 1) {
            g_arrive1 = 0;
            __threadfence();
            atomicAdd(&g_release1, 1u);
        } else {
            while (*rel == old) { }
        }
        __threadfence();
    }
    __syncthreads();
}

__device__ __forceinline__ float bond_e(float r) {
    float dr  = r - OH_BOND_EQ;
    float adr = dr * OH_BOND_ALPHA;
    return 0.5f * OH_BOND_K * dr * dr * (1.0f - adr + adr * adr * (7.0f / 12.0f));
}

// Numerical-Recipes erfcc, relative error ~1e-6 in f32, x >= 0.
__device__ __forceinline__ float fast_erfc(float x) {
    float t = __fdividef(1.0f, fmaf(0.5f, x, 1.0f));
    float p = fmaf(t, 0.17087277f, -0.82215223f);
    p = fmaf(t, p,  1.48851587f);
    p = fmaf(t, p, -1.13520398f);
    p = fmaf(t, p,  0.27886807f);
    p = fmaf(t, p, -0.18628806f);
    p = fmaf(t, p,  0.09678418f);
    p = fmaf(t, p,  0.37409196f);
    p = fmaf(t, p,  1.00002368f);
    p = fmaf(t, p, -1.26551223f);
    return t * __expf(fmaf(-x, x, p));
}

// 4 consecutive pairs, loaded as 5 x 16B vectors
struct VB {
    int4   vi, vj;
    float4 d0, d1, d2;
};

__device__ __forceinline__ void load_group(VB& b,
                                           const int4* __restrict__ ni4,
                                           const int4* __restrict__ nj4,
                                           const float4* __restrict__ dij4,
                                           int g) {
    b.vi = __ldcs(ni4 + g);
    b.vj = __ldcs(nj4 + g);
    b.d0 = __ldcs(dij4 + 3 * g + 0);
    b.d1 = __ldcs(dij4 + 3 * g + 1);
    b.d2 = __ldcs(dij4 + 3 * g + 2);
}

__device__ __forceinline__ float compute_group(const VB& b) {
    const float4 f4z = make_float4(0.0f, 0.0f, 0.0f, 0.0f);
    int ia[4] = {b.vi.x, b.vi.y, b.vi.z, b.vi.w};
    int ja[4] = {b.vj.x, b.vj.y, b.vj.z, b.vj.w};
    float dx[4] = {b.d0.x, b.d0.w, b.d1.z, b.d2.y};
    float dy[4] = {b.d0.y, b.d1.x, b.d1.w, b.d2.z};
    float dz[4] = {b.d0.z, b.d1.y, b.d2.x, b.d2.w};

    float facc = 0.0f;
    #pragma unroll
    for (int k = 0; k < 4; k++) {
        int mi = ia[k] / 3, mj = ja[k] / 3;
        bool iO = (ia[k] == 3 * mi);
        bool jO = (ja[k] == 3 * mj);

        // gathers: lanes hit nearly-consecutive molecules -> few lines, L1-hot
        float4 gi = iO ? g_om[mi] : f4z;
        float4 gj = jO ? g_om[mj] : f4z;

        float ox = dx[k] + gj.x - gi.x;
        float oy = dy[k] + gj.y - gi.y;
        float oz = dz[k] + gj.z - gi.z;

        float qq = (iO ? F_QO : F_QH) * (jO ? F_QO : F_QH);

        float md2  = ox * ox + oy * oy + oz * oz;
        float rinv = rsqrtf(md2);
        float md   = md2 * rinv;
        facc += F_PREF * qq * fast_erfc(md * F_INVSS) * rinv;

        if (iO && jO) {                      // warp-coherent (list is run-blocked)
            float r2 = dx[k] * dx[k] + dy[k] * dy[k] + dz[k] * dz[k];
            float r6 = r2 * r2 * r2;
            float i6 = __fdividef(F_SIG6, r6);
            facc += F_4EPS * (i6 * i6 - i6) + F_SHIFT;
        }
    }
    return facc;
}

// ---------------- fused kernel ----------------
__global__ __launch_bounds__(TB, BPSM)
void k_fused(const float* __restrict__ dij,
             const int* __restrict__ ni,
             const int* __restrict__ nj,
             int n, int n_mol,
             float* __restrict__ out) {
    const int tid  = threadIdx.x;
    const int gtid = blockIdx.x * TB + tid;
    double acc = 0.0;

    // ---- Phase 1: per-molecule terms + M-site offsets ----
    // Pair-list order: pair m = (O_m,H1_m) = doh1[m]; pair n_mol+m = (O_m,H2_m) = doh2[m]
    if (gtid < n_mol) {
        int m = gtid;
        const float* p1 = dij + 3 * m;
        const float* p2 = dij + 3 * (n_mol + m);
        float ax = p1[0], ay = p1[1], az = p1[2];
        float bx = p2[0], by = p2[1], bz = p2[2];

        float r1 = sqrtf(ax * ax + ay * ay + az * az);
        float r2 = sqrtf(bx * bx + by * by + bz * bz);
        float eb = bond_e(r1) + bond_e(r2);

        float dotab = ax * bx + ay * by + az * bz;
        float ang = acosf(dotab / (r1 * r2));
        float da = ang - HOH_ANGLE_EQ;
        eb += 0.5f * HOH_ANGLE_K * da * da;

        float ox = F_OMF * (ax + bx);
        float oy = F_OMF * (ay + by);
        float oz = F_OMF * (az + bz);
        g_om[m] = make_float4(ox, oy, oz, 0.0f);

        float m1x = ax - ox, m1y = ay - oy, m1z = az - oz;
        float m2x = bx - ox, m2y = by - oy, m2z = bz - oz;
        float hhx = ax - bx, hhy = ay - by, hhz = az - bz;
        float inv_mh = rsqrtf(m1x * m1x + m1y * m1y + m1z * m1z)
                     + rsqrtf(m2x * m2x + m2y * m2y + m2z * m2z);
        float inv_hh = rsqrtf(hhx * hhx + hhy * hhy + hhz * hhz);
        float eself = (inv_mh * F_QO + inv_hh * F_QH) * F_QH * F_PREF;
        acc = (double)(eb - eself);
    }

    grid_barrier();   // g_om globally visible

    // ---- Phase 2: vectorized + pipelined pair stream ----
    const int nthreads = NB * TB;
    const int n4 = n >> 2;
    const int4*   ni4  = (const int4*)ni;
    const int4*   nj4  = (const int4*)nj;
    const float4* dij4 = (const float4*)dij;

    int g = gtid;
    bool v = (g < n4);
    VB cur;
    if (v) load_group(cur, ni4, nj4, dij4, g);

    while (v) {
        int  gn = g + nthreads;
        bool vn = (gn < n4);

        VB nxt;
        if (vn) load_group(nxt, ni4, nj4, dij4, gn);  // 80B in flight during compute

        acc += (double)compute_group(cur);

        cur = nxt;
        g = gn;
        v = vn;
    }

    // tail pairs (n % 4), last block, scalar
    if (blockIdx.x == NB - 1) {
        const float4 f4z = make_float4(0.0f, 0.0f, 0.0f, 0.0f);
        for (int p = (n4 << 2) + tid; p < n; p += TB) {
            int i = ni[p], j = nj[p];
            int mi = i / 3, mj = j / 3;
            bool iO = (i == 3 * mi), jO = (j == 3 * mj);
            const float* q = dij + 3 * p;
            float dx = q[0], dy = q[1], dz = q[2];
            float4 gi = iO ? g_om[mi] : f4z;
            float4 gj = jO ? g_om[mj] : f4z;
            float ox = dx + gj.x - gi.x;
            float oy = dy + gj.y - gi.y;
            float oz = dz + gj.z - gi.z;
            float qq = (iO ? F_QO : F_QH) * (jO ? F_QO : F_QH);
            float md2  = ox * ox + oy * oy + oz * oz;
            float rinv = rsqrtf(md2);
            float md   = md2 * rinv;
            float e    = F_PREF * qq * fast_erfc(md * F_INVSS) * rinv;
            if (iO && jO) {
                float r2 = dx * dx + dy * dy + dz * dz;
                float r6 = r2 * r2 * r2;
                float i6 = __fdividef(F_SIG6, r6);
                e += F_4EPS * (i6 * i6 - i6) + F_SHIFT;
            }
            acc += (double)e;
        }
    }

    // ---- Reduce: block -> global, last block writes result ----
    #pragma unroll
    for (int o = 16; o > 0; o >>= 1)
        acc += __shfl_down_sync(0xffffffffu, acc, o);
    __shared__ double s_red[TB / 32];
    int lane = tid & 31;
    int w    = tid >> 5;
    if (lane == 0) s_red[w] = acc;
    __syncthreads();
    if (w == 0) {
        acc = (lane < TB / 32) ? s_red[lane] : 0.0;
        #pragma unroll
        for (int o = 16; o > 0; o >>= 1)
            acc += __shfl_down_sync(0xffffffffu, acc, o);
        if (lane == 0) {
            atomicAdd(&g_energy, acc);
            __threadfence();
            unsigned t = atomicAdd(&g_arrive2, 1u);
            if (t == NB - 1) {
                g_arrive2 = 0;
                unsigned long long vv =
                    atomicExch((unsigned long long*)&g_energy, 0ULL);
                out[0] = (float)__longlong_as_double(vv);
            }
        }
    }
}

// ---------------- launch ----------------
extern "C" void kernel_launch(void* const* d_in, const int* in_sizes, int n_in,
                              void* d_out, int out_size) {
    const float* dij = (const float*)d_in[0];
    const int*   ni  = (const int*)d_in[2];
    const int*   nj  = (const int*)d_in[3];
    int n_pairs = in_sizes[2];
    int n_mol   = in_sizes[1] / 3;
    float* out  = (float*)d_out;

    k_fused<<<NB, TB>>>(dij, ni, nj, n_pairs, n_mol, out);
}